// round 5
// baseline (speedup 1.0000x reference)
#include <cuda_runtime.h>

// BezierToImageLayer — sparse Gaussian splat, round 5.
// R5 vs R4 (74.2us) / best R3 (69.7us):
//  - NSPLIT back to 4 (R4's NSPLIT=8 doubled per-CTA zero/reduce overhead: regression)
//  - keep R4 body: LDS.64 column-pair RMW + fused 2-MUFU exponent
//  - sample points staged in smem: 1 broadcast LDS.64 per sample instead of 2 SHFLs
//  - float4 (LDS.128) reduce epilogue
//  - keep fused last-CTA combine (no separate combine kernel)

#define BDIM     128
#define NWARPS   4
#define NSPLIT   4
#define WPIX     60
#define AROWS    67                         // rows -3..63
#define STRIDE   68                         // 68/2=34 ≡ 2 (mod 16): 2-phase LDS.64, conflict-free
#define RPAD     3
#define CPAD     4
#define NSAMP    30
#define NCURVE   160
#define CPT      (NCURVE / NSPLIT)          // 40 curves per task
#define CPW      (CPT / NWARPS)             // 10 curves per warp
#define COPY_W   (AROWS * STRIDE)           // 4556 floats
#define ACC_WORDS (NWARPS * COPY_W)         // 18224 floats = 72896 B
#define SMEM_WORDS (ACC_WORDS + NWARPS * 64)  // + staged sample points (float2 x32/warp)

#define NBATCH   256
#define IMG      (WPIX * WPIX)

__device__ float g_scratch[NBATCH * NSPLIT * IMG];   // 14.7 MB partials (L2-hot)
__device__ int   g_cnt[NBATCH];                      // zero-init; reset by last CTA

__device__ __forceinline__ float ex2f(float a) {
    float r; asm("ex2.approx.f32 %0, %1;" : "=f"(r) : "f"(a)); return r;
}

__global__ __launch_bounds__(BDIM, 3)
void bezier_splat_kernel(const float* __restrict__ x, float* __restrict__ out)
{
    extern __shared__ float acc[];   // [NWARPS][AROWS][STRIDE] + sample staging

    const int task = blockIdx.x;          // 0..1023
    const int b    = task >> 2;
    const int part = task & (NSPLIT - 1);
    const int tid  = threadIdx.x;
    const int w    = tid >> 5;
    const int lane = tid & 31;

    // ---- zero private accumulators ----
    float4* az = (float4*)acc;
    for (int i = tid; i < ACC_WORDS / 4; i += BDIM)
        az[i] = make_float4(0.f, 0.f, 0.f, 0.f);
    __syncthreads();

    float* __restrict__ my = acc + w * COPY_W + RPAD * STRIDE + CPAD;
    float2* __restrict__ samp = (float2*)(acc + ACC_WORDS) + w * 32;

    const int ra3 = (lane >> 2) + 3;   // row residue (mod 8), pre-biased
    const int pc  = lane & 3;          // column-pair residue (mod 4)

    // ---- per-lane Bezier basis (lane == sample index n), pixel units ----
    const int   n  = (lane < NSAMP) ? lane : (NSAMP - 1);
    const float u  = (float)n * (1.0f / (float)NSAMP);
    const float t  = 2.0f*u*u*u - 3.0f*u*u + 2.0f*u;
    const float t2 = t * t;
    const float t3 = t2 * t;
    const float tb = 1.0f - t;
    const float b0 = 60.0f * t3;
    const float b1 = 180.0f * (t2 - t3);
    const float b2 = 180.0f * (t3 - 2.0f*t2 + t);
    const float b3 = 60.0f * tb * tb * tb;

    const float C2 = -2.0037431123457827f;   // -(5000/3600)*log2(e)

    const float* __restrict__ xb = x + ((size_t)b * NCURVE + part * CPT) * 8;

    for (int c = 0; c < CPW; ++c) {
        const float* ct = xb + (w + NWARPS * c) * 8;

        // this lane's sample point on the curve, pixel units, in [0,60)
        const float Xn = b0*ct[0] + b1*ct[2] + b2*ct[4] + b3*ct[6];
        const float Yn = b0*ct[1] + b1*ct[3] + b2*ct[5] + b3*ct[7];

        __syncwarp();                        // WAR: prev curve's reads done
        if (lane < NSAMP) samp[lane] = make_float2(Xn, Yn);
        __syncwarp();

        #pragma unroll 10
        for (int s = 0; s < NSAMP; ++s) {
            const float2 XY = samp[s];       // broadcast LDS.64
            const float Xp = XY.x, Yp = XY.y;

            const int mi = (int)Xp;          // in [0,59], trunc == floor
            const int mj = (int)Yp;

            // row: i in [mi-3, mi+4], i ≡ ra (mod 8)
            const int i  = mi - 3 + ((ra3 - mi) & 7);
            // col-pairs: P in [P0, P0+3], P ≡ pc (mod 4); cols 2P, 2P+1
            const int P0 = (mj - 3) >> 1;
            const int P  = P0 + ((pc - P0) & 3);

            const float dx  = (float)i       - Xp;
            const float dy1 = (float)(2 * P) - Yp;

            const float sq = fmaf(dy1, dy1, dx * dx);
            const float e1 = sq * C2;
            const float td = fmaf(dy1, 2.0f * C2, C2);   // C2*(dy1+1)^2 - C2*dy1^2
            const float g1 = ex2f(e1);
            const float g2 = ex2f(e1 + td);

            float2* __restrict__ p = (float2*)(my + i * STRIDE + 2 * P);
            float2 v = *p;
            v.x += g1;
            v.y += g2;
            *p = v;
        }
    }
    __syncthreads();

    // ---- reduce 4 private copies -> scratch partial (float4) ----
    float4* __restrict__ sp4 = (float4*)(g_scratch + (size_t)task * IMG);
    const float* __restrict__ a0 = acc + RPAD * STRIDE + CPAD;
    for (int q = tid; q < IMG / 4; q += BDIM) {          // 900 quads
        const int i = q / (WPIX / 4);
        const int k = q - i * (WPIX / 4);
        const int o = (i * STRIDE + 4 * k);
        float4 s0 = *(const float4*)(a0 + o);
        #pragma unroll
        for (int ww = 1; ww < NWARPS; ++ww) {
            const float4 v = *(const float4*)(a0 + ww * COPY_W + o);
            s0.x += v.x; s0.y += v.y; s0.z += v.z; s0.w += v.w;
        }
        sp4[q] = s0;
    }

    // ---- last task of this batch combines the 4 partials ----
    __threadfence();
    __syncthreads();
    __shared__ int s_last;
    if (tid == 0) {
        int old = atomicAdd(&g_cnt[b], 1);
        s_last = (old == NSPLIT - 1);
    }
    __syncthreads();
    if (s_last) {
        __threadfence();   // acquire: see all tasks' scratch writes
        const float4* __restrict__ base =
            (const float4*)(g_scratch + (size_t)b * NSPLIT * IMG);
        float4* __restrict__ ob = (float4*)(out + (size_t)b * IMG);
        for (int q = tid; q < IMG / 4; q += BDIM) {
            float4 s0 = base[q];
            #pragma unroll
            for (int k = 1; k < NSPLIT; ++k) {
                const float4 v = base[k * (IMG / 4) + q];
                s0.x += v.x; s0.y += v.y; s0.z += v.z; s0.w += v.w;
            }
            s0.x = fminf(s0.x, 1.0f);
            s0.y = fminf(s0.y, 1.0f);
            s0.z = fminf(s0.z, 1.0f);
            s0.w = fminf(s0.w, 1.0f);
            ob[q] = s0;
        }
        if (tid == 0) g_cnt[b] = 0;   // reset for next graph replay
    }
}

extern "C" void kernel_launch(void* const* d_in, const int* in_sizes, int n_in,
                              void* d_out, int out_size)
{
    (void)in_sizes; (void)n_in; (void)out_size;
    const float* x = (const float*)d_in[0];
    float* out     = (float*)d_out;

    cudaFuncSetAttribute(bezier_splat_kernel,
                         cudaFuncAttributeMaxDynamicSharedMemorySize,
                         SMEM_WORDS * (int)sizeof(float));

    bezier_splat_kernel<<<NBATCH * NSPLIT, BDIM, SMEM_WORDS * (int)sizeof(float)>>>(x, out);
}

// round 6
// speedup vs baseline: 1.3558x; 1.3558x over previous
#include <cuda_runtime.h>

// BezierToImageLayer — sparse Gaussian splat, round 6.
// R6 = best-of assembly:
//  - R4 body: LDS.64 column-pair RMW + fused 2-MUFU exponent + SHFL broadcast
//    (R5's smem-staged samples created a false LDS/STS alias dependency: reverted)
//  - NSPLIT=4 (R4's NSPLIT=8 doubled per-CTA zero/reduce overhead: reverted)
//  - float4 reduce epilogue (kept from R5)
//  - fused last-CTA combine, no separate kernel (kept from R4)

#define BDIM     128
#define NWARPS   4
#define NSPLIT   4
#define WPIX     60
#define AROWS    67                         // rows -3..63
#define STRIDE   68                         // 68/2=34 ≡ 2 (mod 16): conflict-free LDS.64
#define RPAD     3
#define CPAD     4
#define NSAMP    30
#define NCURVE   160
#define CPT      (NCURVE / NSPLIT)          // 40 curves per task
#define CPW      (CPT / NWARPS)             // 10 curves per warp
#define COPY_W   (AROWS * STRIDE)           // 4556 floats
#define ACC_WORDS (NWARPS * COPY_W)         // 18224 floats = 72896 B

#define NBATCH   256
#define IMG      (WPIX * WPIX)

__device__ float g_scratch[NBATCH * NSPLIT * IMG];   // 14.7 MB partials (L2-hot)
__device__ int   g_cnt[NBATCH];                      // zero-init; reset by last CTA

__device__ __forceinline__ float ex2f(float a) {
    float r; asm("ex2.approx.f32 %0, %1;" : "=f"(r) : "f"(a)); return r;
}

__global__ __launch_bounds__(BDIM, 3)
void bezier_splat_kernel(const float* __restrict__ x, float* __restrict__ out)
{
    extern __shared__ float acc[];   // [NWARPS][AROWS][STRIDE], per-warp private

    const int task = blockIdx.x;          // 0..1023
    const int b    = task >> 2;
    const int part = task & (NSPLIT - 1);
    const int tid  = threadIdx.x;
    const int w    = tid >> 5;
    const int lane = tid & 31;

    // ---- zero private accumulators ----
    float4* az = (float4*)acc;
    for (int i = tid; i < ACC_WORDS / 4; i += BDIM)
        az[i] = make_float4(0.f, 0.f, 0.f, 0.f);
    __syncthreads();

    float* __restrict__ my = acc + w * COPY_W + RPAD * STRIDE + CPAD;

    const int ra3 = (lane >> 2) + 3;   // row residue (mod 8), pre-biased
    const int pc  = lane & 3;          // column-pair residue (mod 4)

    // ---- per-lane Bezier basis (lane == sample index n), pixel units ----
    const int   n  = (lane < NSAMP) ? lane : (NSAMP - 1);
    const float u  = (float)n * (1.0f / (float)NSAMP);
    const float t  = 2.0f*u*u*u - 3.0f*u*u + 2.0f*u;
    const float t2 = t * t;
    const float t3 = t2 * t;
    const float tb = 1.0f - t;
    const float b0 = 60.0f * t3;
    const float b1 = 180.0f * (t2 - t3);
    const float b2 = 180.0f * (t3 - 2.0f*t2 + t);
    const float b3 = 60.0f * tb * tb * tb;

    const float C2 = -2.0037431123457827f;   // -(5000/3600)*log2(e)

    const float* __restrict__ xb = x + ((size_t)b * NCURVE + part * CPT) * 8;

    for (int c = 0; c < CPW; ++c) {
        const float* ct = xb + (w + NWARPS * c) * 8;

        // this lane's sample point on the curve, pixel units, in [0,60)
        const float Xn = b0*ct[0] + b1*ct[2] + b2*ct[4] + b3*ct[6];
        const float Yn = b0*ct[1] + b1*ct[3] + b2*ct[5] + b3*ct[7];

        #pragma unroll 10
        for (int s = 0; s < NSAMP; ++s) {
            const float Xp = __shfl_sync(0xffffffffu, Xn, s);
            const float Yp = __shfl_sync(0xffffffffu, Yn, s);

            const int mi = (int)Xp;          // in [0,59], trunc == floor
            const int mj = (int)Yp;

            // row: i in [mi-3, mi+4], i ≡ ra (mod 8)
            const int i  = mi - 3 + ((ra3 - mi) & 7);
            // col-pairs: P in [P0, P0+3], P ≡ pc (mod 4); cols 2P, 2P+1
            const int P0 = (mj - 3) >> 1;
            const int P  = P0 + ((pc - P0) & 3);

            const float dx  = (float)i       - Xp;
            const float dy1 = (float)(2 * P) - Yp;

            const float sq = fmaf(dy1, dy1, dx * dx);
            const float e1 = sq * C2;
            const float td = fmaf(dy1, 2.0f * C2, C2);   // C2*(dy1+1)^2 - C2*dy1^2
            const float g1 = ex2f(e1);
            const float g2 = ex2f(e1 + td);

            float2* __restrict__ p = (float2*)(my + i * STRIDE + 2 * P);
            float2 v = *p;
            v.x += g1;
            v.y += g2;
            *p = v;
        }
    }
    __syncthreads();

    // ---- reduce 4 private copies -> scratch partial (float4) ----
    float4* __restrict__ sp4 = (float4*)(g_scratch + (size_t)task * IMG);
    const float* __restrict__ a0 = acc + RPAD * STRIDE + CPAD;
    for (int q = tid; q < IMG / 4; q += BDIM) {          // 900 quads
        const int i = q / (WPIX / 4);
        const int k = q - i * (WPIX / 4);
        const int o = i * STRIDE + 4 * k;
        float4 s0 = *(const float4*)(a0 + o);
        #pragma unroll
        for (int ww = 1; ww < NWARPS; ++ww) {
            const float4 v = *(const float4*)(a0 + ww * COPY_W + o);
            s0.x += v.x; s0.y += v.y; s0.z += v.z; s0.w += v.w;
        }
        sp4[q] = s0;
    }

    // ---- last task of this batch combines the 4 partials ----
    __threadfence();
    __syncthreads();
    __shared__ int s_last;
    if (tid == 0) {
        int old = atomicAdd(&g_cnt[b], 1);
        s_last = (old == NSPLIT - 1);
    }
    __syncthreads();
    if (s_last) {
        __threadfence();   // acquire: see all tasks' scratch writes
        const float4* __restrict__ base =
            (const float4*)(g_scratch + (size_t)b * NSPLIT * IMG);
        float4* __restrict__ ob = (float4*)(out + (size_t)b * IMG);
        for (int q = tid; q < IMG / 4; q += BDIM) {
            float4 s0 = base[q];
            #pragma unroll
            for (int k = 1; k < NSPLIT; ++k) {
                const float4 v = base[k * (IMG / 4) + q];
                s0.x += v.x; s0.y += v.y; s0.z += v.z; s0.w += v.w;
            }
            s0.x = fminf(s0.x, 1.0f);
            s0.y = fminf(s0.y, 1.0f);
            s0.z = fminf(s0.z, 1.0f);
            s0.w = fminf(s0.w, 1.0f);
            ob[q] = s0;
        }
        if (tid == 0) g_cnt[b] = 0;   // reset for next graph replay
    }
}

extern "C" void kernel_launch(void* const* d_in, const int* in_sizes, int n_in,
                              void* d_out, int out_size)
{
    (void)in_sizes; (void)n_in; (void)out_size;
    const float* x = (const float*)d_in[0];
    float* out     = (float*)d_out;

    cudaFuncSetAttribute(bezier_splat_kernel,
                         cudaFuncAttributeMaxDynamicSharedMemorySize,
                         ACC_WORDS * (int)sizeof(float));

    bezier_splat_kernel<<<NBATCH * NSPLIT, BDIM, ACC_WORDS * (int)sizeof(float)>>>(x, out);
}